// round 14
// baseline (speedup 1.0000x reference)
#include <cuda_runtime.h>
#include <cuda_fp16.h>
#include <cstdint>
#include <math.h>

#define NSAMP 8192
#define HIDN  256
#define SPC   16                 // samples per CTA
#define GRID  (NSAMP / SPC)      // 512

// Jet channels: 0=val, 1=d/dx0, 2=d/dx1, 3=d/dt, 4=dx0dx0, 5=dx0dx1, 6=dx1dx1
__device__ __align__(256) __half g_Wt[3][HIDN * HIDN];  // W^T fp16: [n][k]
__device__ double g_acc[5];
__device__ unsigned g_done = 0;

// SMEM layout: A region (112 rows x 512B, swizzled) then B double buffer
#define ABYTES 57344             // 112 * 512
#define BCH    16384             // B chunk: 256 rows x 64B (K=32)
#define SMEMT  (ABYTES + 2 * BCH)   // 90112

// ---------------------------------------------------------------------------
__device__ __forceinline__ uint32_t smem_u32(const void* p) {
    uint32_t a;
    asm("{ .reg .u64 t; cvta.to.shared.u64 t, %1; cvt.u32.u64 %0, t; }" : "=r"(a) : "l"(p));
    return a;
}
// Swizzled ROW BASES. Column offsets (< row stride) combine with XOR (no carries).
__device__ __forceinline__ uint32_t arow(uint32_t r) { return r * 512 ^ ((r & 7) << 4); }
__device__ __forceinline__ uint32_t brow(uint32_t r) { return r * 64  ^ ((r & 3) << 4); }

__device__ __forceinline__ void cpasync16(uint32_t s, const void* g) {
    asm volatile("cp.async.cg.shared.global [%0], [%1], 16;" :: "r"(s), "l"(g));
}
#define CP_COMMIT() asm volatile("cp.async.commit_group;" ::: "memory")

__device__ __forceinline__ void ldsm_x4(uint32_t* r, uint32_t a) {
    asm volatile("ldmatrix.sync.aligned.m8n8.x4.shared.b16 {%0,%1,%2,%3}, [%4];"
                 : "=r"(r[0]), "=r"(r[1]), "=r"(r[2]), "=r"(r[3]) : "r"(a));
}
__device__ __forceinline__ void mma16816h(uint32_t* d, const uint32_t* a,
                                          uint32_t b0, uint32_t b1) {
    asm volatile(
        "mma.sync.aligned.m16n8k16.row.col.f16.f16.f16.f16 "
        "{%0,%1}, {%2,%3,%4,%5}, {%6,%7}, {%0,%1};"
        : "+r"(d[0]), "+r"(d[1])
        : "r"(a[0]), "r"(a[1]), "r"(a[2]), "r"(a[3]), "r"(b0), "r"(b1));
}

// ---------------------------------------------------------------------------
__global__ void k_prepW(const float* __restrict__ W1, const float* __restrict__ W2,
                        const float* __restrict__ W3) {
    int w = blockIdx.z;
    const float* W = (w == 0) ? W1 : ((w == 1) ? W2 : W3);
    int n = blockIdx.x, k = threadIdx.x;
    g_Wt[w][n * HIDN + k] = __float2half(W[k * HIDN + n]);
    if (w == 0 && n == 0 && k < 5) g_acc[k] = 0.0;
}

// ---------------------------------------------------------------------------
// Fused whole-network kernel: layer0 jets -> 3x (GEMM + jet-tanh) with
// activations resident in SMEM -> physics epilogue -> global reduction.
__global__ void __launch_bounds__(256, 2) k_fused(
        const float* __restrict__ W0, const float* __restrict__ b0,
        const float* __restrict__ x,  const float* __restrict__ t,
        const float* __restrict__ b1, const float* __restrict__ b2,
        const float* __restrict__ b3,
        const float* __restrict__ W4, const float* __restrict__ b4,
        float* __restrict__ out) {
    extern __shared__ char smem[];
    uint32_t sb = smem_u32(smem);
    int tid = threadIdx.x;
    int warp = tid >> 5, lane = tid & 31;
    int n0 = blockIdx.x * SPC;

    const __half* Bws[3] = { g_Wt[0], g_Wt[1], g_Wt[2] };
    const float* biases[3] = { b1, b2, b3 };

    auto loadB = [&](const __half* Bw, int c) {
        uint32_t base = sb + ABYTES + (c & 1) * BCH;
        const __half* src = Bw + c * 32;
#pragma unroll
        for (int idx = tid; idx < 1024; idx += 256) {
            uint32_t r = idx >> 2, u = idx & 3;
            cpasync16(base + (brow(r) ^ (u * 16)), src + (size_t)r * HIDN + u * 8);
        }
        CP_COMMIT();
    };

    // prefetch layer-1 weights while computing layer-0 jets
    loadB(Bws[0], 0);
    loadB(Bws[0], 1);

    // ---- layer 0: input jets into resident A ----
    for (int i = tid; i < SPC * HIDN; i += 256) {
        int nl = i >> 8, j = i & 255;
        int n = n0 + nl;
        float x0 = x[2 * n], x1 = x[2 * n + 1], tv = t[n];
        float w0 = W0[j], w1 = W0[HIDN + j], w2 = W0[2 * HIDN + j];
        float zv = fmaf(x0, w0, fmaf(x1, w1, fmaf(tv, w2, b0[j])));
        float y = tanhf(zv);
        float yp = 1.0f - y * y;
        float ypp = -2.0f * y * yp;
        uint32_t r = nl * 7;
        uint32_t jb = j * 2;
        *(__half*)(smem + (arow(r + 0) ^ jb)) = __float2half(y);
        *(__half*)(smem + (arow(r + 1) ^ jb)) = __float2half(yp * w0);
        *(__half*)(smem + (arow(r + 2) ^ jb)) = __float2half(yp * w1);
        *(__half*)(smem + (arow(r + 3) ^ jb)) = __float2half(yp * w2);
        *(__half*)(smem + (arow(r + 4) ^ jb)) = __float2half(ypp * w0 * w0);
        *(__half*)(smem + (arow(r + 5) ^ jb)) = __float2half(ypp * w0 * w1);
        *(__half*)(smem + (arow(r + 6) ^ jb)) = __float2half(ypp * w1 * w1);
    }
    __syncthreads();

    int l8 = lane & 7;
    int qm8  = ((lane >> 3) & 1) * 8;   // +8 row for mats 1,3
    uint32_t qk16 = (lane >> 4) * 16;   // +16B (k+8) for mats 2,3

    uint32_t abase[7];
#pragma unroll
    for (int mt = 0; mt < 7; mt++)
        abase[mt] = arow(mt * 16 + qm8 + l8) ^ qk16;
    uint32_t bb0 = sb + ABYTES + (brow(warp * 32 + qm8 + l8) ^ qk16);
    uint32_t bb1 = sb + ABYTES + (brow(warp * 32 + 16 + qm8 + l8) ^ qk16);

    // ---- 3 hidden layers ----
#pragma unroll 1
    for (int layer = 0; layer < 3; layer++) {
        uint32_t acc[7][4][2];
#pragma unroll
        for (int mt = 0; mt < 7; mt++)
#pragma unroll
            for (int nt = 0; nt < 4; nt++) { acc[mt][nt][0] = 0u; acc[mt][nt][1] = 0u; }

#pragma unroll
        for (int c = 0; c < 8; c++) {
            if (c < 7) asm volatile("cp.async.wait_group 1;" ::: "memory");
            else       asm volatile("cp.async.wait_group 0;" ::: "memory");
            __syncthreads();
            uint32_t bsel = (uint32_t)((c & 1) * BCH);

            // load ALL B fragments for this chunk (both ks) up front
            uint32_t bf[2][2][4];
#pragma unroll
            for (int ks = 0; ks < 2; ks++) {
                ldsm_x4(bf[ks][0], (bb0 + bsel) ^ (uint32_t)(ks * 32));
                ldsm_x4(bf[ks][1], (bb1 + bsel) ^ (uint32_t)(ks * 32));
            }
            __syncthreads();   // B buffer free for the incoming cp.async

            // issue next-next chunk load; it overlaps the MMA stream below
            if (c + 2 < 8) loadB(Bws[layer], c + 2);
            else if (c == 7 && layer < 2) {
                loadB(Bws[layer + 1], 0);
                loadB(Bws[layer + 1], 1);
            }

#pragma unroll
            for (int ks = 0; ks < 2; ks++) {
                uint32_t acol = (uint32_t)(c * 64 + ks * 32);   // constant
#pragma unroll
                for (int mt = 0; mt < 7; mt++) {
                    uint32_t af[4];
                    ldsm_x4(af, sb + (abase[mt] ^ acol));
                    mma16816h(acc[mt][0], af, bf[ks][0][0], bf[ks][0][2]);
                    mma16816h(acc[mt][1], af, bf[ks][0][1], bf[ks][0][3]);
                    mma16816h(acc[mt][2], af, bf[ks][1][0], bf[ks][1][2]);
                    mma16816h(acc[mt][3], af, bf[ks][1][1], bf[ks][1][3]);
                }
            }
        }
        __syncthreads();   // all MMAs done before overwriting A

        // stage z (pre-activation) in place over A
#pragma unroll
        for (int mt = 0; mt < 7; mt++)
#pragma unroll
            for (int nt = 0; nt < 4; nt++)
#pragma unroll
                for (int e = 0; e < 2; e++) {
                    uint32_t r = mt * 16 + (lane >> 2) + e * 8;
                    uint32_t colb = (warp * 32 + nt * 8 + ((lane & 3) << 1)) * 2;
                    *(uint32_t*)(smem + (arow(r) ^ colb)) = acc[mt][nt][e];
                }
        __syncthreads();

        // jet-tanh activation in place
        const float* bias = biases[layer];
        for (int i = tid; i < SPC * HIDN; i += 256) {
            int nl = i >> 8, j = i & 255;
            uint32_t r = nl * 7;
            uint32_t jb = j * 2;
            float zv  = __half2float(*(__half*)(smem + (arow(r + 0) ^ jb))) + bias[j];
            float zg1 = __half2float(*(__half*)(smem + (arow(r + 1) ^ jb)));
            float zg2 = __half2float(*(__half*)(smem + (arow(r + 2) ^ jb)));
            float zg3 = __half2float(*(__half*)(smem + (arow(r + 3) ^ jb)));
            float zs11 = __half2float(*(__half*)(smem + (arow(r + 4) ^ jb)));
            float zs12 = __half2float(*(__half*)(smem + (arow(r + 5) ^ jb)));
            float zs22 = __half2float(*(__half*)(smem + (arow(r + 6) ^ jb)));
            float y = tanhf(zv);
            float yp = 1.0f - y * y;
            float ypp = -2.0f * y * yp;
            *(__half*)(smem + (arow(r + 0) ^ jb)) = __float2half(y);
            *(__half*)(smem + (arow(r + 1) ^ jb)) = __float2half(yp * zg1);
            *(__half*)(smem + (arow(r + 2) ^ jb)) = __float2half(yp * zg2);
            *(__half*)(smem + (arow(r + 3) ^ jb)) = __float2half(yp * zg3);
            *(__half*)(smem + (arow(r + 4) ^ jb)) = __float2half(fmaf(ypp * zg1, zg1, yp * zs11));
            *(__half*)(smem + (arow(r + 5) ^ jb)) = __float2half(fmaf(ypp * zg1, zg2, yp * zs12));
            *(__half*)(smem + (arow(r + 6) ^ jb)) = __float2half(fmaf(ypp * zg2, zg2, yp * zs22));
        }
        __syncthreads();
    }

    // ---- physics epilogue (B region is idle scratch) ----
    float*  w4s  = (float*)(smem + ABYTES);
    float*  b4s  = (float*)(smem + ABYTES + 3072);
    double* sacc = (double*)(smem + ABYTES + 3072 + 64);
    if (tid < 5) sacc[tid] = 0.0;
    for (int i = tid; i < 768; i += 256) w4s[i] = W4[i];
    if (tid < 3) b4s[tid] = b4[tid];
    __syncthreads();

    float wreg[8][3];
#pragma unroll
    for (int i = 0; i < 8; i++) {
        int k = lane * 8 + i;
        wreg[i][0] = w4s[k * 3 + 0];
        wreg[i][1] = w4s[k * 3 + 1];
        wreg[i][2] = w4s[k * 3 + 2];
    }

    for (int s = 0; s < 2; s++) {
        int nl = warp * 2 + s;
        int n = n0 + nl;

        float o[7][3];
#pragma unroll
        for (int c = 0; c < 7; c++)
#pragma unroll
            for (int a = 0; a < 3; a++) o[c][a] = 0.0f;

#pragma unroll
        for (int c = 0; c < 7; c++) {
            int4 v = *(const int4*)(smem + (arow(nl * 7 + c) ^ (lane * 16)));
            const __half2* h2 = (const __half2*)&v;
#pragma unroll
            for (int g = 0; g < 4; g++) {
                float2 f2 = __half22float2(h2[g]);
#pragma unroll
                for (int a = 0; a < 3; a++) {
                    o[c][a] = fmaf(f2.x, wreg[2 * g][a], o[c][a]);
                    o[c][a] = fmaf(f2.y, wreg[2 * g + 1][a], o[c][a]);
                }
            }
        }
#pragma unroll
        for (int c = 0; c < 7; c++)
#pragma unroll
            for (int a = 0; a < 3; a++)
#pragma unroll
                for (int off = 16; off > 0; off >>= 1)
                    o[c][a] += __shfl_xor_sync(0xFFFFFFFFu, o[c][a], off);

        if (lane == 0) {
            float s0  = o[0][0] + b4s[0];
            float s1v = o[0][1] + b4s[1];
            float s2v = o[0][2] + b4s[2];
            float D00 = o[1][0], D01 = o[2][0], D0t = o[3][0];
            float S000 = o[4][0], S011 = o[6][0];
            float D10 = o[1][1], D11 = o[2][1];
            float S100 = o[4][1], S101 = o[5][1], S111 = o[6][1];
            float D20 = o[1][2], D21 = o[2][2];
            float S200 = o[4][2], S201 = o[5][2], S211 = o[6][2];

            float x1 = x[2 * n + 1];
            float tt = t[n];
            float q  = x1 * (x1 - 1.0f);
            float qp = 2.0f * x1 - 1.0f;
            float t3 = tt / 3.0f;

            float ux0 = t3 * q * D10;
            float ux1 = t3 * (qp * s1v + q * D11);
            float uy0 = tt * q * D20;
            float uy1 = tt * (qp * s2v + q * D21) + tt;

            float e00 = ux0, e11 = uy1, e01 = 0.5f * (ux1 + uy0);

            float ux00 = t3 * q * S100;
            float ux01 = t3 * (qp * D10 + q * S101);
            float ux11 = t3 * (2.0f * s1v + 2.0f * qp * D11 + q * S111);
            float uy00 = tt * q * S200;
            float uy01 = tt * (qp * D20 + q * S201);
            float uy11 = tt * (2.0f * s2v + 2.0f * qp * D21 + q * S211);

            float e00_0 = ux00, e00_1 = ux01;
            float e11_0 = uy01, e11_1 = uy11;
            float e01_0 = 0.5f * (ux01 + uy00);
            float e01_1 = 0.5f * (ux11 + uy01);

            float trc  = e00 + e11;
            float tr_0 = e00_0 + e11_0;
            float tr_1 = e00_1 + e11_1;

            float phi = 1.0f / (1.0f + expf(-s0));
            float sp  = phi * (1.0f - phi);
            float spp = sp * (1.0f - 2.0f * phi);
            float p0 = sp * D00, p1 = sp * D01, pt = sp * D0t;
            float p00 = spp * D00 * D00 + sp * S000;
            float p11 = spp * D01 * D01 + sp * S011;
            float lap = p00 + p11;

            float A  = fmaxf(trc, 0.0f);
            float Bn = fmaxf(-trc, 0.0f);
            float ppos = (trc > 0.0f) ? 1.0f : 0.0f;
            float pneg = (trc < 0.0f) ? 1.0f : 0.0f;
            float dd = e00 - e11;

            float omp = 1.0f - phi;
            float h   = omp * omp;
            float g   = h + 1e-6f;
            float hp0 = -2.0f * omp * p0;
            float hp1 = -2.0f * omp * p1;

            float P00 = 2.0f * A + dd;
            float P11 = 2.0f * A - dd;
            float P01 = 2.0f * e01;
            float s00 = g * P00 - 2.0f * Bn;
            float s11c = g * P11 - 2.0f * Bn;
            float s01 = g * P01;

            float P00_0 = 2.0f * ppos * tr_0 + (e00_0 - e11_0);
            float P11_1 = 2.0f * ppos * tr_1 - (e00_1 - e11_1);
            float P01_0 = 2.0f * e01_0;
            float P01_1 = 2.0f * e01_1;

            float s00_0 = hp0 * P00 + g * P00_0 + 2.0f * pneg * tr_0;
            float s11_1 = hp1 * P11 + g * P11_1 + 2.0f * pneg * tr_1;
            float s01_0 = hp0 * P01 + g * P01_0;
            float s01_1 = hp1 * P01 + g * P01_1;

            float res0 = hp0 * s00 + h * s00_0 + hp1 * s01 + h * s01_1;
            float res1 = hp0 * s01 + h * s01_0 + hp1 * s11c + h * s11_1;

            float psip = A * A + 0.5f * dd * dd + 2.0f * e01 * e01;
            float psin = Bn * Bn;

            const float GCc = 0.0027f, Lc = 0.02f;
            float pf = GCc * (phi / Lc - Lc * lap) - 2.0f * omp * psip;
            float dphidt = pt;
            bool mask_pos = (fabsf(dphidt) <= 1e-3f) && (fabsf(phi - 1.0f) > 1e-3f);
            bool mask_neg = (fabsf(phi - 1.0f) <= 1e-3f);
            float respf = mask_pos ? fmaxf(-pf, 0.0f) : (mask_neg ? fmaxf(pf, 0.0f) : pf);

            float rese = omp * 2.0f * psip + psin
                       + GCc * (phi * phi / (2.0f * Lc) + 0.5f * Lc * (p0 * p0 + p1 * p1));
            float rirr = fmaxf(-dphidt, 0.0f);

            atomicAdd(&sacc[0], (double)(res0 * res0));
            atomicAdd(&sacc[1], (double)(res1 * res1));
            atomicAdd(&sacc[2], (double)(respf * respf));
            atomicAdd(&sacc[3], (double)rese);
            atomicAdd(&sacc[4], (double)rirr);
        }
    }
    __syncthreads();
    if (tid < 5) atomicAdd(&g_acc[tid], sacc[tid]);

    // last CTA finalizes outputs
    if (tid == 0) {
        __threadfence();
        unsigned v = atomicAdd(&g_done, 1u);
        if (v == gridDim.x - 1) {
            g_done = 0;   // reset for graph replay
            double S0 = g_acc[0], S1 = g_acc[1], Spf = g_acc[2];
            double Se = g_acc[3], Si = g_acc[4];
            double Nn = (double)NSAMP;
            double mse0 = S0 / Nn, mse1 = S1 / Nn;
            double m  = 0.5 * (mse0 + mse1);
            double w0 = m / (mse0 + 1e-6);
            double w1 = m / (mse1 + 1e-6);
            out[0] = (float)(w0 * mse0 + w1 * mse1);
            out[1] = (float)(Spf / Nn);
            out[2] = (float)log(Se);
            out[3] = (float)(Si / Nn);
        }
    }
}

// ---------------------------------------------------------------------------
extern "C" void kernel_launch(void* const* d_in, const int* in_sizes, int n_in,
                              void* d_out, int out_size) {
    const float *W[5], *b[5];
    if (n_in >= 2 && in_sizes[1] == HIDN) {
        for (int i = 0; i < 5; i++) {
            W[i] = (const float*)d_in[2 * i];
            b[i] = (const float*)d_in[2 * i + 1];
        }
    } else {
        for (int i = 0; i < 5; i++) {
            W[i] = (const float*)d_in[i];
            b[i] = (const float*)d_in[5 + i];
        }
    }
    const float* x = (const float*)d_in[10];
    const float* t = (const float*)d_in[11];

    static bool attr_done = false;
    if (!attr_done) {
        cudaFuncSetAttribute(k_fused, cudaFuncAttributeMaxDynamicSharedMemorySize, SMEMT);
        attr_done = true;
    }

    k_prepW<<<dim3(HIDN, 1, 3), HIDN>>>(W[1], W[2], W[3]);
    k_fused<<<GRID, 256, SMEMT>>>(W[0], b[0], x, t, b[1], b[2], b[3],
                                  W[4], b[4], (float*)d_out);
}

// round 15
// speedup vs baseline: 1.1408x; 1.1408x over previous
#include <cuda_runtime.h>
#include <cuda_fp16.h>
#include <cstdint>
#include <math.h>

#define NSAMP 8192
#define HIDN  256
#define MTOT  (7 * NSAMP)       // 57344 rows, interleaved: row = n*7 + c
#define MT    112               // rows per CTA tile (16 samples * 7 channels)
#define SPC   16

// Jet channels: 0=val, 1=d/dx0, 2=d/dx1, 3=d/dt, 4=dx0dx0, 5=dx0dx1, 6=dx1dx1
__device__ __align__(256) __half g_A0[MTOT * HIDN];   // ping
__device__ __align__(256) __half g_A1[MTOT * HIDN];   // pong
__device__ __align__(256) __half g_Wt[3][HIDN * HIDN]; // W^T fp16: [n][k]
__device__ double g_acc[5];
__device__ unsigned g_done = 0;

// ---------------------------------------------------------------------------
__device__ __forceinline__ uint32_t smem_u32(const void* p) {
    uint32_t a;
    asm("{ .reg .u64 t; cvta.to.shared.u64 t, %1; cvt.u32.u64 %0, t; }" : "=r"(a) : "l"(p));
    return a;
}
__device__ __forceinline__ uint32_t sw128(uint32_t o) { return o ^ ((o >> 3) & 0x70); }

__device__ __forceinline__ void cpasync16(uint32_t s, const void* g) {
    asm volatile("cp.async.cg.shared.global [%0], [%1], 16;" :: "r"(s), "l"(g));
}
#define CP_COMMIT() asm volatile("cp.async.commit_group;" ::: "memory")

__device__ __forceinline__ void ldsm_x4(uint32_t* r, uint32_t a) {
    asm volatile("ldmatrix.sync.aligned.m8n8.x4.shared.b16 {%0,%1,%2,%3}, [%4];"
                 : "=r"(r[0]), "=r"(r[1]), "=r"(r[2]), "=r"(r[3]) : "r"(a));
}
// fp16-accumulating MMA: d = {c0c1, c2c3} packed half2 regs
__device__ __forceinline__ void mma16816h(uint32_t* d, const uint32_t* a,
                                          uint32_t b0, uint32_t b1) {
    asm volatile(
        "mma.sync.aligned.m16n8k16.row.col.f16.f16.f16.f16 "
        "{%0,%1}, {%2,%3,%4,%5}, {%6,%7}, {%0,%1};"
        : "+r"(d[0]), "+r"(d[1])
        : "r"(a[0]), "r"(a[1]), "r"(a[2]), "r"(a[3]), "r"(b0), "r"(b1));
}

// ---------------------------------------------------------------------------
// Merged: layer0 jets (blocks 0..NSAMP-1) + weight transpose/convert + acc
// zero (blocks NSAMP..NSAMP+767).
__global__ void k_prep0(const float* __restrict__ W0, const float* __restrict__ b0,
                        const float* __restrict__ x,  const float* __restrict__ t,
                        const float* __restrict__ W1, const float* __restrict__ W2,
                        const float* __restrict__ W3) {
    int blk = blockIdx.x;
    int j = threadIdx.x;
    if (blk >= NSAMP) {
        int wb = blk - NSAMP;          // 0..767
        int w = wb >> 8;               // weight matrix id
        int n = wb & 255;
        const float* W = (w == 0) ? W1 : ((w == 1) ? W2 : W3);
        g_Wt[w][n * HIDN + j] = __float2half(W[j * HIDN + n]);
        if (wb == 0 && j < 5) g_acc[j] = 0.0;
        return;
    }
    int n = blk;
    float x0 = x[2 * n], x1 = x[2 * n + 1], tv = t[n];
    float w0 = W0[j], w1 = W0[HIDN + j], w2 = W0[2 * HIDN + j];
    float zv = fmaf(x0, w0, fmaf(x1, w1, fmaf(tv, w2, b0[j])));
    float y = tanhf(zv);
    float yp = 1.0f - y * y;
    float ypp = -2.0f * y * yp;
    size_t base = ((size_t)n * 7) * HIDN + j;
    g_A0[base]            = __float2half(y);
    g_A0[base + HIDN]     = __float2half(yp * w0);
    g_A0[base + 2 * HIDN] = __float2half(yp * w1);
    g_A0[base + 3 * HIDN] = __float2half(yp * w2);
    g_A0[base + 4 * HIDN] = __float2half(ypp * w0 * w0);
    g_A0[base + 5 * HIDN] = __float2half(ypp * w0 * w1);
    g_A0[base + 6 * HIDN] = __float2half(ypp * w1 * w1);
}

// ---------------------------------------------------------------------------
// Fused fp16 GEMM + jet-tanh activation layer (ping-pong A buffers).
// CTA: 256 threads / 8 warps; tile 112 x 256 (full N); warp tile 7mt x 4nt.
// fp16 accumulators. K in 4 chunks of 64, 2-stage cp.async double buffer.
#define ACH   14336                 // A chunk: 112 rows x 128B
#define BCH   32768                 // B chunk: 256 rows x 128B
#define BUF   (ACH + BCH)           // 47104
#define SMEMT (2 * BUF)             // 94208
#define ZS    264                   // z staging stride in halfs

__global__ void __launch_bounds__(256, 2) k_gemm(const __half* __restrict__ Asrc,
                                                 __half* __restrict__ Adst,
                                                 const __half* __restrict__ Bw,
                                                 const float* __restrict__ bias) {
    extern __shared__ char smem[];
    uint32_t sb = smem_u32(smem);
    int tid = threadIdx.x;
    int warp = tid >> 5, lane = tid & 31;
    int row0 = blockIdx.x * MT;

    uint32_t acc[7][4][2];   // fp16x2 accumulators
#pragma unroll
    for (int mt = 0; mt < 7; mt++)
#pragma unroll
        for (int nt = 0; nt < 4; nt++) { acc[mt][nt][0] = 0u; acc[mt][nt][1] = 0u; }

    auto load_chunk = [&](int c) {
        uint32_t base = sb + (c & 1) * BUF;
        int k0 = c * 64;
#pragma unroll
        for (int idx = tid; idx < 896; idx += 256) {
            int r = idx >> 3, u = idx & 7;
            cpasync16(base + sw128(r * 128 + u * 16),
                      Asrc + (size_t)(row0 + r) * HIDN + k0 + u * 8);
        }
#pragma unroll
        for (int idx = tid; idx < 2048; idx += 256) {
            int r = idx >> 3, u = idx & 7;
            cpasync16(base + ACH + sw128(r * 128 + u * 16),
                      Bw + (size_t)r * HIDN + k0 + u * 8);
        }
        CP_COMMIT();
    };

    load_chunk(0);
    load_chunk(1);

    int l8 = lane & 7;
    int qm8  = ((lane >> 3) & 1) * 8;   // +8 row for mats 1,3
    uint32_t qk16 = (lane >> 4) * 16;   // +16B (k+8) for mats 2,3

    // swizzled base offsets at ks=0; per-ks address = base ^ (ks*32)
    uint32_t aoff0 = sw128((qm8 + l8) * 128) ^ qk16;
    uint32_t boff0 = ACH + (sw128((warp * 32 + qm8 + l8) * 128) ^ qk16);
    uint32_t boff1 = ACH + (sw128((warp * 32 + 16 + qm8 + l8) * 128) ^ qk16);

    uint32_t af[2][4];       // rolling A fragments
    uint32_t bf[2][8];       // double-buffered B fragments (per ks)

#pragma unroll
    for (int c = 0; c < 4; c++) {
        if (c < 3) asm volatile("cp.async.wait_group 1;" ::: "memory");
        else       asm volatile("cp.async.wait_group 0;" ::: "memory");
        __syncthreads();

        uint32_t bufb = sb + (c & 1) * BUF;

        // prime pipeline: B frags for ks=0, A frag for mt=0
        ldsm_x4(&bf[0][0], bufb + boff0);
        ldsm_x4(&bf[0][4], bufb + boff1);
        ldsm_x4(af[0], bufb + aoff0);

        int p = 0;   // current A slot
#pragma unroll
        for (int ks = 0; ks < 4; ks++) {
            uint32_t kxn = ((ks + 1) & 3) * 32;
            const uint32_t* bcur = bf[ks & 1];
#pragma unroll
            for (int mt = 0; mt < 7; mt++) {
                // prefetch next A fragment (next mt, or mt0 of next ks)
                if (mt < 6) {
                    uint32_t kx = ks * 32;
                    ldsm_x4(af[p ^ 1], bufb + ((aoff0 + (mt + 1) * 2048) ^ kx));
                } else if (ks < 3) {
                    ldsm_x4(af[p ^ 1], bufb + (aoff0 ^ kxn));
                }
                // prefetch next B fragments early in the mt stream
                if (mt == 1 && ks < 3) {
                    ldsm_x4(&bf[(ks + 1) & 1][0], bufb + (boff0 ^ kxn));
                    ldsm_x4(&bf[(ks + 1) & 1][4], bufb + (boff1 ^ kxn));
                }
                const uint32_t* a = af[p];
                mma16816h(acc[mt][0], a, bcur[0], bcur[2]);
                mma16816h(acc[mt][1], a, bcur[1], bcur[3]);
                mma16816h(acc[mt][2], a, bcur[4], bcur[6]);
                mma16816h(acc[mt][3], a, bcur[5], bcur[7]);
                p ^= 1;
            }
        }
        if (c + 2 < 4) { __syncthreads(); load_chunk(c + 2); }
    }
    __syncthreads();

    // ---- epilogue: fp16 accums -> smem staging, jet activation, fp16 out ----
    __half* zb = (__half*)smem;
#pragma unroll
    for (int mt = 0; mt < 7; mt++)
#pragma unroll
        for (int nt = 0; nt < 4; nt++)
#pragma unroll
            for (int e = 0; e < 2; e++) {   // e: row-octet (d0 row, d1 row+8)
                int r = mt * 16 + (lane >> 2) + e * 8;
                int col = warp * 32 + nt * 8 + ((lane & 3) << 1);
                *(uint32_t*)(zb + r * ZS + col) = acc[mt][nt][e];
            }
    __syncthreads();

    // half2-vectorized activation: each thread handles a (j, j+1) column pair
    for (int i = tid; i < SPC * (HIDN / 2); i += 256) {
        int nl = i >> 7, jp = (i & 127) * 2;
        const __half* zrow = zb + (nl * 7) * ZS + jp;
        float2 zv2  = __half22float2(*(const __half2*)(zrow));
        float2 zg1  = __half22float2(*(const __half2*)(zrow + ZS));
        float2 zg2  = __half22float2(*(const __half2*)(zrow + 2 * ZS));
        float2 zg3  = __half22float2(*(const __half2*)(zrow + 3 * ZS));
        float2 zs11 = __half22float2(*(const __half2*)(zrow + 4 * ZS));
        float2 zs12 = __half22float2(*(const __half2*)(zrow + 5 * ZS));
        float2 zs22 = __half22float2(*(const __half2*)(zrow + 6 * ZS));
        float b0v = bias[jp], b1v = bias[jp + 1];

        float ya = tanhf(zv2.x + b0v),      yb = tanhf(zv2.y + b1v);
        float ypa = 1.0f - ya * ya,         ypb = 1.0f - yb * yb;
        float yppa = -2.0f * ya * ypa,      yppb = -2.0f * yb * ypb;

        __half2* dst = (__half2*)(Adst + ((size_t)(row0 + nl * 7)) * HIDN + jp);
        dst[0]                    = __floats2half2_rn(ya, yb);
        dst[HIDN / 2]             = __floats2half2_rn(ypa * zg1.x, ypb * zg1.y);
        dst[2 * (HIDN / 2)]       = __floats2half2_rn(ypa * zg2.x, ypb * zg2.y);
        dst[3 * (HIDN / 2)]       = __floats2half2_rn(ypa * zg3.x, ypb * zg3.y);
        dst[4 * (HIDN / 2)]       = __floats2half2_rn(
            fmaf(yppa * zg1.x, zg1.x, ypa * zs11.x),
            fmaf(yppb * zg1.y, zg1.y, ypb * zs11.y));
        dst[5 * (HIDN / 2)]       = __floats2half2_rn(
            fmaf(yppa * zg1.x, zg2.x, ypa * zs12.x),
            fmaf(yppb * zg1.y, zg2.y, ypb * zs12.y));
        dst[6 * (HIDN / 2)]       = __floats2half2_rn(
            fmaf(yppa * zg2.x, zg2.x, ypa * zs22.x),
            fmaf(yppb * zg2.y, zg2.y, ypb * zs22.y));
    }
}

// ---------------------------------------------------------------------------
// Physics epilogue: final 256->3 layer on all 7 jet channels + residuals.
// Vectorized int4 loads of H; per-lane W4 slice cached in registers.
// Last block computes the final 4 outputs (merged finalize).
__global__ void __launch_bounds__(256) k_epi(const __half* __restrict__ H,
                                             const float* __restrict__ W4,
                                             const float* __restrict__ b4,
                                             const float* __restrict__ x,
                                             const float* __restrict__ t,
                                             float* __restrict__ out) {
    __shared__ float  w4s[768];
    __shared__ float  b4s[3];
    __shared__ double sacc[5];
    int tid = threadIdx.x;
    if (tid < 5) sacc[tid] = 0.0;
    for (int i = tid; i < 768; i += 256) w4s[i] = W4[i];
    if (tid < 3) b4s[tid] = b4[tid];
    __syncthreads();

    int warp = tid >> 5, lane = tid & 31;
    int n = blockIdx.x * 8 + warp;

    float wreg[8][3];
#pragma unroll
    for (int i = 0; i < 8; i++) {
        int k = lane * 8 + i;
        wreg[i][0] = w4s[k * 3 + 0];
        wreg[i][1] = w4s[k * 3 + 1];
        wreg[i][2] = w4s[k * 3 + 2];
    }

    float o[7][3];
#pragma unroll
    for (int c = 0; c < 7; c++)
#pragma unroll
        for (int a = 0; a < 3; a++) o[c][a] = 0.0f;

    const int4* Hrow = (const int4*)(H + ((size_t)n * 7) * HIDN);
#pragma unroll
    for (int c = 0; c < 7; c++) {
        int4 v = Hrow[c * (HIDN / 8) + lane];   // 8 halfs, coalesced 16B
        const __half2* h2 = (const __half2*)&v;
#pragma unroll
        for (int g = 0; g < 4; g++) {
            float2 f2 = __half22float2(h2[g]);
#pragma unroll
            for (int a = 0; a < 3; a++) {
                o[c][a] = fmaf(f2.x, wreg[2 * g][a], o[c][a]);
                o[c][a] = fmaf(f2.y, wreg[2 * g + 1][a], o[c][a]);
            }
        }
    }
#pragma unroll
    for (int c = 0; c < 7; c++)
#pragma unroll
        for (int a = 0; a < 3; a++)
#pragma unroll
            for (int off = 16; off > 0; off >>= 1)
                o[c][a] += __shfl_xor_sync(0xFFFFFFFFu, o[c][a], off);

    if (lane == 0) {
        float s0  = o[0][0] + b4s[0];
        float s1v = o[0][1] + b4s[1];
        float s2v = o[0][2] + b4s[2];
        float D00 = o[1][0], D01 = o[2][0], D0t = o[3][0];
        float S000 = o[4][0], S011 = o[6][0];
        float D10 = o[1][1], D11 = o[2][1];
        float S100 = o[4][1], S101 = o[5][1], S111 = o[6][1];
        float D20 = o[1][2], D21 = o[2][2];
        float S200 = o[4][2], S201 = o[5][2], S211 = o[6][2];

        float x1 = x[2 * n + 1];
        float tt = t[n];
        float q  = x1 * (x1 - 1.0f);
        float qp = 2.0f * x1 - 1.0f;
        float t3 = tt / 3.0f;

        float ux0 = t3 * q * D10;
        float ux1 = t3 * (qp * s1v + q * D11);
        float uy0 = tt * q * D20;
        float uy1 = tt * (qp * s2v + q * D21) + tt;

        float e00 = ux0, e11 = uy1, e01 = 0.5f * (ux1 + uy0);

        float ux00 = t3 * q * S100;
        float ux01 = t3 * (qp * D10 + q * S101);
        float ux11 = t3 * (2.0f * s1v + 2.0f * qp * D11 + q * S111);
        float uy00 = tt * q * S200;
        float uy01 = tt * (qp * D20 + q * S201);
        float uy11 = tt * (2.0f * s2v + 2.0f * qp * D21 + q * S211);

        float e00_0 = ux00, e00_1 = ux01;
        float e11_0 = uy01, e11_1 = uy11;
        float e01_0 = 0.5f * (ux01 + uy00);
        float e01_1 = 0.5f * (ux11 + uy01);

        float trc  = e00 + e11;
        float tr_0 = e00_0 + e11_0;
        float tr_1 = e00_1 + e11_1;

        float phi = 1.0f / (1.0f + expf(-s0));
        float sp  = phi * (1.0f - phi);
        float spp = sp * (1.0f - 2.0f * phi);
        float p0 = sp * D00, p1 = sp * D01, pt = sp * D0t;
        float p00 = spp * D00 * D00 + sp * S000;
        float p11 = spp * D01 * D01 + sp * S011;
        float lap = p00 + p11;

        float A  = fmaxf(trc, 0.0f);
        float Bn = fmaxf(-trc, 0.0f);
        float ppos = (trc > 0.0f) ? 1.0f : 0.0f;
        float pneg = (trc < 0.0f) ? 1.0f : 0.0f;
        float dd = e00 - e11;

        float omp = 1.0f - phi;
        float h   = omp * omp;
        float g   = h + 1e-6f;
        float hp0 = -2.0f * omp * p0;
        float hp1 = -2.0f * omp * p1;

        float P00 = 2.0f * A + dd;
        float P11 = 2.0f * A - dd;
        float P01 = 2.0f * e01;
        float s00 = g * P00 - 2.0f * Bn;
        float s11c = g * P11 - 2.0f * Bn;
        float s01 = g * P01;

        float P00_0 = 2.0f * ppos * tr_0 + (e00_0 - e11_0);
        float P11_1 = 2.0f * ppos * tr_1 - (e00_1 - e11_1);
        float P01_0 = 2.0f * e01_0;
        float P01_1 = 2.0f * e01_1;

        float s00_0 = hp0 * P00 + g * P00_0 + 2.0f * pneg * tr_0;
        float s11_1 = hp1 * P11 + g * P11_1 + 2.0f * pneg * tr_1;
        float s01_0 = hp0 * P01 + g * P01_0;
        float s01_1 = hp1 * P01 + g * P01_1;

        float res0 = hp0 * s00 + h * s00_0 + hp1 * s01 + h * s01_1;
        float res1 = hp0 * s01 + h * s01_0 + hp1 * s11c + h * s11_1;

        float psip = A * A + 0.5f * dd * dd + 2.0f * e01 * e01;
        float psin = Bn * Bn;

        const float GCc = 0.0027f, Lc = 0.02f;
        float pf = GCc * (phi / Lc - Lc * lap) - 2.0f * omp * psip;
        float dphidt = pt;
        bool mask_pos = (fabsf(dphidt) <= 1e-3f) && (fabsf(phi - 1.0f) > 1e-3f);
        bool mask_neg = (fabsf(phi - 1.0f) <= 1e-3f);
        float respf = mask_pos ? fmaxf(-pf, 0.0f) : (mask_neg ? fmaxf(pf, 0.0f) : pf);

        float rese = omp * 2.0f * psip + psin
                   + GCc * (phi * phi / (2.0f * Lc) + 0.5f * Lc * (p0 * p0 + p1 * p1));
        float rirr = fmaxf(-dphidt, 0.0f);

        atomicAdd(&sacc[0], (double)(res0 * res0));
        atomicAdd(&sacc[1], (double)(res1 * res1));
        atomicAdd(&sacc[2], (double)(respf * respf));
        atomicAdd(&sacc[3], (double)rese);
        atomicAdd(&sacc[4], (double)rirr);
    }
    __syncthreads();
    if (tid < 5) atomicAdd(&g_acc[tid], sacc[tid]);

    // merged finalize: last block to finish computes the outputs
    if (tid == 0) {
        __threadfence();
        unsigned v = atomicAdd(&g_done, 1u);
        if (v == gridDim.x - 1) {
            g_done = 0;   // reset for graph replay
            double S0 = g_acc[0], S1 = g_acc[1], Spf = g_acc[2];
            double Se = g_acc[3], Si = g_acc[4];
            double Nn = (double)NSAMP;
            double mse0 = S0 / Nn, mse1 = S1 / Nn;
            double m  = 0.5 * (mse0 + mse1);
            double w0 = m / (mse0 + 1e-6);
            double w1 = m / (mse1 + 1e-6);
            out[0] = (float)(w0 * mse0 + w1 * mse1);
            out[1] = (float)(Spf / Nn);
            out[2] = (float)log(Se);
            out[3] = (float)(Si / Nn);
        }
    }
}

// ---------------------------------------------------------------------------
extern "C" void kernel_launch(void* const* d_in, const int* in_sizes, int n_in,
                              void* d_out, int out_size) {
    const float *W[5], *b[5];
    if (n_in >= 2 && in_sizes[1] == HIDN) {
        for (int i = 0; i < 5; i++) {
            W[i] = (const float*)d_in[2 * i];
            b[i] = (const float*)d_in[2 * i + 1];
        }
    } else {
        for (int i = 0; i < 5; i++) {
            W[i] = (const float*)d_in[i];
            b[i] = (const float*)d_in[5 + i];
        }
    }
    const float* x = (const float*)d_in[10];
    const float* t = (const float*)d_in[11];

    __half *pA0, *pA1, *pW;
    cudaGetSymbolAddress((void**)&pA0, g_A0);
    cudaGetSymbolAddress((void**)&pA1, g_A1);
    cudaGetSymbolAddress((void**)&pW,  g_Wt);

    static bool attr_done = false;
    if (!attr_done) {
        cudaFuncSetAttribute(k_gemm, cudaFuncAttributeMaxDynamicSharedMemorySize, SMEMT);
        attr_done = true;
    }

    k_prep0<<<NSAMP + 768, 256>>>(W[0], b[0], x, t, W[1], W[2], W[3]);

    const int GRID = MTOT / MT;      // 512
    k_gemm<<<GRID, 256, SMEMT>>>(pA0, pA1, pW,                   b[1]);
    k_gemm<<<GRID, 256, SMEMT>>>(pA1, pA0, pW + HIDN * HIDN,     b[2]);
    k_gemm<<<GRID, 256, SMEMT>>>(pA0, pA1, pW + 2 * HIDN * HIDN, b[3]);

    k_epi<<<NSAMP / 8, 256>>>(pA1, W[4], b[4], x, t, (float*)d_out);
}

// round 16
// speedup vs baseline: 1.2090x; 1.0597x over previous
#include <cuda_runtime.h>
#include <cuda_fp16.h>
#include <cstdint>
#include <math.h>

#define NSAMP 8192
#define HIDN  256
#define MTOT  (7 * NSAMP)       // 57344 rows, interleaved: row = n*7 + c
#define MT    112               // rows per CTA tile (16 samples * 7 channels)
#define SPC   16

// Jet channels: 0=val, 1=d/dx0, 2=d/dx1, 3=d/dt, 4=dx0dx0, 5=dx0dx1, 6=dx1dx1
__device__ __align__(256) __half g_A0[MTOT * HIDN];   // ping
__device__ __align__(256) __half g_A1[MTOT * HIDN];   // pong
__device__ __align__(256) __half g_Wt[3][HIDN * HIDN]; // W^T fp16: [n][k]
__device__ double g_acc[5];
__device__ unsigned g_done = 0;

// ---------------------------------------------------------------------------
__device__ __forceinline__ uint32_t smem_u32(const void* p) {
    uint32_t a;
    asm("{ .reg .u64 t; cvta.to.shared.u64 t, %1; cvt.u32.u64 %0, t; }" : "=r"(a) : "l"(p));
    return a;
}
__device__ __forceinline__ uint32_t sw128(uint32_t o) { return o ^ ((o >> 3) & 0x70); }

__device__ __forceinline__ void cpasync16(uint32_t s, const void* g) {
    asm volatile("cp.async.cg.shared.global [%0], [%1], 16;" :: "r"(s), "l"(g));
}
#define CP_COMMIT() asm volatile("cp.async.commit_group;" ::: "memory")

__device__ __forceinline__ void ldsm_x4(uint32_t* r, uint32_t a) {
    asm volatile("ldmatrix.sync.aligned.m8n8.x4.shared.b16 {%0,%1,%2,%3}, [%4];"
                 : "=r"(r[0]), "=r"(r[1]), "=r"(r[2]), "=r"(r[3]) : "r"(a));
}
// fp16-accumulating MMA: d = {c0c1, c2c3} packed half2 regs
__device__ __forceinline__ void mma16816h(uint32_t* d, const uint32_t* a,
                                          uint32_t b0, uint32_t b1) {
    asm volatile(
        "mma.sync.aligned.m16n8k16.row.col.f16.f16.f16.f16 "
        "{%0,%1}, {%2,%3,%4,%5}, {%6,%7}, {%0,%1};"
        : "+r"(d[0]), "+r"(d[1])
        : "r"(a[0]), "r"(a[1]), "r"(a[2]), "r"(a[3]), "r"(b0), "r"(b1));
}

// ---------------------------------------------------------------------------
// Merged: layer0 jets (blocks 0..NSAMP-1) + weight transpose/convert + acc
// zero (blocks NSAMP..NSAMP+767).
__global__ void k_prep0(const float* __restrict__ W0, const float* __restrict__ b0,
                        const float* __restrict__ x,  const float* __restrict__ t,
                        const float* __restrict__ W1, const float* __restrict__ W2,
                        const float* __restrict__ W3) {
    int blk = blockIdx.x;
    int j = threadIdx.x;
    if (blk >= NSAMP) {
        int wb = blk - NSAMP;          // 0..767
        int w = wb >> 8;               // weight matrix id
        int n = wb & 255;
        const float* W = (w == 0) ? W1 : ((w == 1) ? W2 : W3);
        g_Wt[w][n * HIDN + j] = __float2half(W[j * HIDN + n]);
        if (wb == 0 && j < 5) g_acc[j] = 0.0;
        return;
    }
    int n = blk;
    float x0 = x[2 * n], x1 = x[2 * n + 1], tv = t[n];
    float w0 = W0[j], w1 = W0[HIDN + j], w2 = W0[2 * HIDN + j];
    float zv = fmaf(x0, w0, fmaf(x1, w1, fmaf(tv, w2, b0[j])));
    float y = tanhf(zv);
    float yp = 1.0f - y * y;
    float ypp = -2.0f * y * yp;
    size_t base = ((size_t)n * 7) * HIDN + j;
    g_A0[base]            = __float2half(y);
    g_A0[base + HIDN]     = __float2half(yp * w0);
    g_A0[base + 2 * HIDN] = __float2half(yp * w1);
    g_A0[base + 3 * HIDN] = __float2half(yp * w2);
    g_A0[base + 4 * HIDN] = __float2half(ypp * w0 * w0);
    g_A0[base + 5 * HIDN] = __float2half(ypp * w0 * w1);
    g_A0[base + 6 * HIDN] = __float2half(ypp * w1 * w1);
}

// ---------------------------------------------------------------------------
// Fused fp16 GEMM + jet-tanh activation layer (ping-pong A buffers).
// CTA: 256 threads / 8 warps; tile 112 x 256 (full N); warp tile 7mt x 4nt.
// fp16 accumulators. K in 4 chunks of 64, 2-stage cp.async double buffer.
// last=1: instead of storing activations, run the physics epilogue inline.
#define ACH   14336                 // A chunk: 112 rows x 128B
#define BCH   32768                 // B chunk: 256 rows x 128B
#define BUF   (ACH + BCH)           // 47104
#define SMEMT (2 * BUF)             // 94208
#define ZS    264                   // z staging stride in halfs (528B = 33*16)

__global__ void __launch_bounds__(256, 2) k_gemm(const __half* __restrict__ Asrc,
                                                 __half* __restrict__ Adst,
                                                 const __half* __restrict__ Bw,
                                                 const float* __restrict__ bias,
                                                 const float* __restrict__ W4,
                                                 const float* __restrict__ b4,
                                                 const float* __restrict__ x,
                                                 const float* __restrict__ t,
                                                 float* __restrict__ out,
                                                 int last) {
    extern __shared__ char smem[];
    uint32_t sb = smem_u32(smem);
    int tid = threadIdx.x;
    int warp = tid >> 5, lane = tid & 31;
    int row0 = blockIdx.x * MT;

    uint32_t acc[7][4][2];   // fp16x2 accumulators
#pragma unroll
    for (int mt = 0; mt < 7; mt++)
#pragma unroll
        for (int nt = 0; nt < 4; nt++) { acc[mt][nt][0] = 0u; acc[mt][nt][1] = 0u; }

    auto load_chunk = [&](int c) {
        uint32_t base = sb + (c & 1) * BUF;
        int k0 = c * 64;
#pragma unroll
        for (int idx = tid; idx < 896; idx += 256) {
            int r = idx >> 3, u = idx & 7;
            cpasync16(base + sw128(r * 128 + u * 16),
                      Asrc + (size_t)(row0 + r) * HIDN + k0 + u * 8);
        }
#pragma unroll
        for (int idx = tid; idx < 2048; idx += 256) {
            int r = idx >> 3, u = idx & 7;
            cpasync16(base + ACH + sw128(r * 128 + u * 16),
                      Bw + (size_t)r * HIDN + k0 + u * 8);
        }
        CP_COMMIT();
    };

    load_chunk(0);
    load_chunk(1);

    int l8 = lane & 7;
    int qm8  = ((lane >> 3) & 1) * 8;   // +8 row for mats 1,3
    uint32_t qk16 = (lane >> 4) * 16;   // +16B (k+8) for mats 2,3

    uint32_t aoff0 = sw128((qm8 + l8) * 128) ^ qk16;
    uint32_t boff0 = ACH + (sw128((warp * 32 + qm8 + l8) * 128) ^ qk16);
    uint32_t boff1 = ACH + (sw128((warp * 32 + 16 + qm8 + l8) * 128) ^ qk16);

    uint32_t af[2][4];       // rolling A fragments
    uint32_t bf[2][8];       // double-buffered B fragments (per ks)

#pragma unroll
    for (int c = 0; c < 4; c++) {
        if (c < 3) asm volatile("cp.async.wait_group 1;" ::: "memory");
        else       asm volatile("cp.async.wait_group 0;" ::: "memory");
        __syncthreads();

        uint32_t bufb = sb + (c & 1) * BUF;

        ldsm_x4(&bf[0][0], bufb + boff0);
        ldsm_x4(&bf[0][4], bufb + boff1);
        ldsm_x4(af[0], bufb + aoff0);

        int p = 0;
#pragma unroll
        for (int ks = 0; ks < 4; ks++) {
            uint32_t kxn = ((ks + 1) & 3) * 32;
            const uint32_t* bcur = bf[ks & 1];
#pragma unroll
            for (int mt = 0; mt < 7; mt++) {
                if (mt < 6) {
                    uint32_t kx = ks * 32;
                    ldsm_x4(af[p ^ 1], bufb + ((aoff0 + (mt + 1) * 2048) ^ kx));
                } else if (ks < 3) {
                    ldsm_x4(af[p ^ 1], bufb + (aoff0 ^ kxn));
                }
                if (mt == 1 && ks < 3) {
                    ldsm_x4(&bf[(ks + 1) & 1][0], bufb + (boff0 ^ kxn));
                    ldsm_x4(&bf[(ks + 1) & 1][4], bufb + (boff1 ^ kxn));
                }
                const uint32_t* a = af[p];
                mma16816h(acc[mt][0], a, bcur[0], bcur[2]);
                mma16816h(acc[mt][1], a, bcur[1], bcur[3]);
                mma16816h(acc[mt][2], a, bcur[4], bcur[6]);
                mma16816h(acc[mt][3], a, bcur[5], bcur[7]);
                p ^= 1;
            }
        }
        if (c + 2 < 4) { __syncthreads(); load_chunk(c + 2); }
    }
    __syncthreads();

    // ---- stage z (pre-activation, fp16) into smem ----
    __half* zb = (__half*)smem;
#pragma unroll
    for (int mt = 0; mt < 7; mt++)
#pragma unroll
        for (int nt = 0; nt < 4; nt++)
#pragma unroll
            for (int e = 0; e < 2; e++) {
                int r = mt * 16 + (lane >> 2) + e * 8;
                int col = warp * 32 + nt * 8 + ((lane & 3) << 1);
                *(uint32_t*)(zb + r * ZS + col) = acc[mt][nt][e];
            }
    __syncthreads();

    if (!last) {
        // half2-vectorized activation -> global fp16
        for (int i = tid; i < SPC * (HIDN / 2); i += 256) {
            int nl = i >> 7, jp = (i & 127) * 2;
            const __half* zrow = zb + (nl * 7) * ZS + jp;
            float2 zv2  = __half22float2(*(const __half2*)(zrow));
            float2 zg1  = __half22float2(*(const __half2*)(zrow + ZS));
            float2 zg2  = __half22float2(*(const __half2*)(zrow + 2 * ZS));
            float2 zg3  = __half22float2(*(const __half2*)(zrow + 3 * ZS));
            float2 zs11 = __half22float2(*(const __half2*)(zrow + 4 * ZS));
            float2 zs12 = __half22float2(*(const __half2*)(zrow + 5 * ZS));
            float2 zs22 = __half22float2(*(const __half2*)(zrow + 6 * ZS));
            float b0v = bias[jp], b1v = bias[jp + 1];

            float ya = tanhf(zv2.x + b0v),  yb = tanhf(zv2.y + b1v);
            float ypa = 1.0f - ya * ya,     ypb = 1.0f - yb * yb;
            float yppa = -2.0f * ya * ypa,  yppb = -2.0f * yb * ypb;

            __half2* dst = (__half2*)(Adst + ((size_t)(row0 + nl * 7)) * HIDN + jp);
            dst[0]              = __floats2half2_rn(ya, yb);
            dst[HIDN / 2]       = __floats2half2_rn(ypa * zg1.x, ypb * zg1.y);
            dst[2 * (HIDN / 2)] = __floats2half2_rn(ypa * zg2.x, ypb * zg2.y);
            dst[3 * (HIDN / 2)] = __floats2half2_rn(ypa * zg3.x, ypb * zg3.y);
            dst[4 * (HIDN / 2)] = __floats2half2_rn(
                fmaf(yppa * zg1.x, zg1.x, ypa * zs11.x),
                fmaf(yppb * zg1.y, zg1.y, ypb * zs11.y));
            dst[5 * (HIDN / 2)] = __floats2half2_rn(
                fmaf(yppa * zg1.x, zg2.x, ypa * zs12.x),
                fmaf(yppb * zg1.y, zg2.y, ypb * zs12.y));
            dst[6 * (HIDN / 2)] = __floats2half2_rn(
                fmaf(yppa * zg2.x, zg2.x, ypa * zs22.x),
                fmaf(yppb * zg2.y, zg2.y, ypb * zs22.y));
        }
        return;
    }

    // ==== last layer: physics epilogue directly from z-staging ====
    double* sacc = (double*)(smem + 60000);   // past zb (112*528=59136), in smem
    if (tid < 5) sacc[tid] = 0.0;
    __syncthreads();

    // per-lane W4 slice (k = lane*8..lane*8+7) and layer-3 bias slice
    float wreg[8][3];
    float breg[8];
#pragma unroll
    for (int i = 0; i < 8; i++) {
        int k = lane * 8 + i;
        wreg[i][0] = W4[k * 3 + 0];
        wreg[i][1] = W4[k * 3 + 1];
        wreg[i][2] = W4[k * 3 + 2];
        breg[i] = bias[k];
    }

    for (int s = 0; s < 2; s++) {
        int nl = warp * 2 + s;
        int n = blockIdx.x * SPC + nl;

        float o[7][3];
#pragma unroll
        for (int c = 0; c < 7; c++)
#pragma unroll
            for (int a = 0; a < 3; a++) o[c][a] = 0.0f;

        const __half* zbase = zb + (nl * 7) * ZS + lane * 8;
#pragma unroll
        for (int g = 0; g < 4; g++) {
            float2 z[7];
#pragma unroll
            for (int c = 0; c < 7; c++)
                z[c] = __half22float2(*(const __half2*)(zbase + c * ZS + g * 2));
#pragma unroll
            for (int e = 0; e < 2; e++) {
                int i = g * 2 + e;
                float zv  = (e ? z[0].y : z[0].x) + breg[i];
                float zg1 = e ? z[1].y : z[1].x;
                float zg2 = e ? z[2].y : z[2].x;
                float zg3 = e ? z[3].y : z[3].x;
                float zs11 = e ? z[4].y : z[4].x;
                float zs12 = e ? z[5].y : z[5].x;
                float zs22 = e ? z[6].y : z[6].x;
                float y = tanhf(zv);
                float yp = 1.0f - y * y;
                float ypp = -2.0f * y * yp;
                float H0 = y;
                float H1 = yp * zg1;
                float H2 = yp * zg2;
                float H3 = yp * zg3;
                float H4 = fmaf(ypp * zg1, zg1, yp * zs11);
                float H5 = fmaf(ypp * zg1, zg2, yp * zs12);
                float H6 = fmaf(ypp * zg2, zg2, yp * zs22);
#pragma unroll
                for (int a = 0; a < 3; a++) {
                    o[0][a] = fmaf(H0, wreg[i][a], o[0][a]);
                    o[1][a] = fmaf(H1, wreg[i][a], o[1][a]);
                    o[2][a] = fmaf(H2, wreg[i][a], o[2][a]);
                    o[3][a] = fmaf(H3, wreg[i][a], o[3][a]);
                    o[4][a] = fmaf(H4, wreg[i][a], o[4][a]);
                    o[5][a] = fmaf(H5, wreg[i][a], o[5][a]);
                    o[6][a] = fmaf(H6, wreg[i][a], o[6][a]);
                }
            }
        }
#pragma unroll
        for (int c = 0; c < 7; c++)
#pragma unroll
            for (int a = 0; a < 3; a++)
#pragma unroll
                for (int off = 16; off > 0; off >>= 1)
                    o[c][a] += __shfl_xor_sync(0xFFFFFFFFu, o[c][a], off);

        if (lane == 0) {
            float s0  = o[0][0] + b4[0];
            float s1v = o[0][1] + b4[1];
            float s2v = o[0][2] + b4[2];
            float D00 = o[1][0], D01 = o[2][0], D0t = o[3][0];
            float S000 = o[4][0], S011 = o[6][0];
            float D10 = o[1][1], D11 = o[2][1];
            float S100 = o[4][1], S101 = o[5][1], S111 = o[6][1];
            float D20 = o[1][2], D21 = o[2][2];
            float S200 = o[4][2], S201 = o[5][2], S211 = o[6][2];

            float x1 = x[2 * n + 1];
            float tt = t[n];
            float q  = x1 * (x1 - 1.0f);
            float qp = 2.0f * x1 - 1.0f;
            float t3 = tt / 3.0f;

            float ux0 = t3 * q * D10;
            float ux1 = t3 * (qp * s1v + q * D11);
            float uy0 = tt * q * D20;
            float uy1 = tt * (qp * s2v + q * D21) + tt;

            float e00 = ux0, e11 = uy1, e01 = 0.5f * (ux1 + uy0);

            float ux00 = t3 * q * S100;
            float ux01 = t3 * (qp * D10 + q * S101);
            float ux11 = t3 * (2.0f * s1v + 2.0f * qp * D11 + q * S111);
            float uy00 = tt * q * S200;
            float uy01 = tt * (qp * D20 + q * S201);
            float uy11 = tt * (2.0f * s2v + 2.0f * qp * D21 + q * S211);

            float e00_0 = ux00, e00_1 = ux01;
            float e11_0 = uy01, e11_1 = uy11;
            float e01_0 = 0.5f * (ux01 + uy00);
            float e01_1 = 0.5f * (ux11 + uy01);

            float trc  = e00 + e11;
            float tr_0 = e00_0 + e11_0;
            float tr_1 = e00_1 + e11_1;

            float phi = 1.0f / (1.0f + expf(-s0));
            float sp  = phi * (1.0f - phi);
            float spp = sp * (1.0f - 2.0f * phi);
            float p0 = sp * D00, p1 = sp * D01, pt = sp * D0t;
            float p00 = spp * D00 * D00 + sp * S000;
            float p11 = spp * D01 * D01 + sp * S011;
            float lap = p00 + p11;

            float A  = fmaxf(trc, 0.0f);
            float Bn = fmaxf(-trc, 0.0f);
            float ppos = (trc > 0.0f) ? 1.0f : 0.0f;
            float pneg = (trc < 0.0f) ? 1.0f : 0.0f;
            float dd = e00 - e11;

            float omp = 1.0f - phi;
            float h   = omp * omp;
            float g   = h + 1e-6f;
            float hp0 = -2.0f * omp * p0;
            float hp1 = -2.0f * omp * p1;

            float P00 = 2.0f * A + dd;
            float P11 = 2.0f * A - dd;
            float P01 = 2.0f * e01;
            float s00 = g * P00 - 2.0f * Bn;
            float s11c = g * P11 - 2.0f * Bn;
            float s01 = g * P01;

            float P00_0 = 2.0f * ppos * tr_0 + (e00_0 - e11_0);
            float P11_1 = 2.0f * ppos * tr_1 - (e00_1 - e11_1);
            float P01_0 = 2.0f * e01_0;
            float P01_1 = 2.0f * e01_1;

            float s00_0 = hp0 * P00 + g * P00_0 + 2.0f * pneg * tr_0;
            float s11_1 = hp1 * P11 + g * P11_1 + 2.0f * pneg * tr_1;
            float s01_0 = hp0 * P01 + g * P01_0;
            float s01_1 = hp1 * P01 + g * P01_1;

            float res0 = hp0 * s00 + h * s00_0 + hp1 * s01 + h * s01_1;
            float res1 = hp0 * s01 + h * s01_0 + hp1 * s11c + h * s11_1;

            float psip = A * A + 0.5f * dd * dd + 2.0f * e01 * e01;
            float psin = Bn * Bn;

            const float GCc = 0.0027f, Lc = 0.02f;
            float pf = GCc * (phi / Lc - Lc * lap) - 2.0f * omp * psip;
            float dphidt = pt;
            bool mask_pos = (fabsf(dphidt) <= 1e-3f) && (fabsf(phi - 1.0f) > 1e-3f);
            bool mask_neg = (fabsf(phi - 1.0f) <= 1e-3f);
            float respf = mask_pos ? fmaxf(-pf, 0.0f) : (mask_neg ? fmaxf(pf, 0.0f) : pf);

            float rese = omp * 2.0f * psip + psin
                       + GCc * (phi * phi / (2.0f * Lc) + 0.5f * Lc * (p0 * p0 + p1 * p1));
            float rirr = fmaxf(-dphidt, 0.0f);

            atomicAdd(&sacc[0], (double)(res0 * res0));
            atomicAdd(&sacc[1], (double)(res1 * res1));
            atomicAdd(&sacc[2], (double)(respf * respf));
            atomicAdd(&sacc[3], (double)rese);
            atomicAdd(&sacc[4], (double)rirr);
        }
    }
    __syncthreads();
    if (tid < 5) atomicAdd(&g_acc[tid], sacc[tid]);

    // merged finalize: last CTA computes the outputs
    if (tid == 0) {
        __threadfence();
        unsigned v = atomicAdd(&g_done, 1u);
        if (v == gridDim.x - 1) {
            g_done = 0;   // reset for graph replay
            double S0 = g_acc[0], S1 = g_acc[1], Spf = g_acc[2];
            double Se = g_acc[3], Si = g_acc[4];
            double Nn = (double)NSAMP;
            double mse0 = S0 / Nn, mse1 = S1 / Nn;
            double m  = 0.5 * (mse0 + mse1);
            double w0 = m / (mse0 + 1e-6);
            double w1 = m / (mse1 + 1e-6);
            out[0] = (float)(w0 * mse0 + w1 * mse1);
            out[1] = (float)(Spf / Nn);
            out[2] = (float)log(Se);
            out[3] = (float)(Si / Nn);
        }
    }
}

// ---------------------------------------------------------------------------
extern "C" void kernel_launch(void* const* d_in, const int* in_sizes, int n_in,
                              void* d_out, int out_size) {
    const float *W[5], *b[5];
    if (n_in >= 2 && in_sizes[1] == HIDN) {
        for (int i = 0; i < 5; i++) {
            W[i] = (const float*)d_in[2 * i];
            b[i] = (const float*)d_in[2 * i + 1];
        }
    } else {
        for (int i = 0; i < 5; i++) {
            W[i] = (const float*)d_in[i];
            b[i] = (const float*)d_in[5 + i];
        }
    }
    const float* x = (const float*)d_in[10];
    const float* t = (const float*)d_in[11];

    __half *pA0, *pA1, *pW;
    cudaGetSymbolAddress((void**)&pA0, g_A0);
    cudaGetSymbolAddress((void**)&pA1, g_A1);
    cudaGetSymbolAddress((void**)&pW,  g_Wt);

    static bool attr_done = false;
    if (!attr_done) {
        cudaFuncSetAttribute(k_gemm, cudaFuncAttributeMaxDynamicSharedMemorySize, SMEMT);
        attr_done = true;
    }

    k_prep0<<<NSAMP + 768, 256>>>(W[0], b[0], x, t, W[1], W[2], W[3]);

    const int GRID = MTOT / MT;      // 512
    k_gemm<<<GRID, 256, SMEMT>>>(pA0, pA1, pW,                   b[1],
                                 W[4], b[4], x, t, (float*)d_out, 0);
    k_gemm<<<GRID, 256, SMEMT>>>(pA1, pA0, pW + HIDN * HIDN,     b[2],
                                 W[4], b[4], x, t, (float*)d_out, 0);
    k_gemm<<<GRID, 256, SMEMT>>>(pA0, pA1, pW + 2 * HIDN * HIDN, b[3],
                                 W[4], b[4], x, t, (float*)d_out, 1);
}

// round 17
// speedup vs baseline: 1.2154x; 1.0053x over previous
#include <cuda_runtime.h>
#include <cuda_fp16.h>
#include <cstdint>
#include <math.h>

#define NSAMP 8192
#define HIDN  256
#define MTOT  (7 * NSAMP)       // 57344 rows, interleaved: row = n*7 + c
#define MT    112               // rows per CTA tile (16 samples * 7 channels)
#define SPC   16

// Jet channels: 0=val, 1=d/dx0, 2=d/dx1, 3=d/dt, 4=dx0dx0, 5=dx0dx1, 6=dx1dx1
__device__ __align__(256) __half g_A0[MTOT * HIDN];   // ping
__device__ __align__(256) __half g_A1[MTOT * HIDN];   // pong
__device__ __align__(256) __half g_Wt[3][HIDN * HIDN]; // W^T fp16: [n][k]
__device__ double g_acc[5];
__device__ unsigned g_done = 0;

// ---------------------------------------------------------------------------
__device__ __forceinline__ uint32_t smem_u32(const void* p) {
    uint32_t a;
    asm("{ .reg .u64 t; cvta.to.shared.u64 t, %1; cvt.u32.u64 %0, t; }" : "=r"(a) : "l"(p));
    return a;
}
__device__ __forceinline__ uint32_t sw128(uint32_t o) { return o ^ ((o >> 3) & 0x70); }

// HW tanh: single-instruction, max rel err ~2^-11 (same order as fp16 rounding)
__device__ __forceinline__ float tanh_hw(float v) {
    float r;
    asm("tanh.approx.f32 %0, %1;" : "=f"(r) : "f"(v));
    return r;
}

__device__ __forceinline__ void cpasync16(uint32_t s, const void* g) {
    asm volatile("cp.async.cg.shared.global [%0], [%1], 16;" :: "r"(s), "l"(g));
}
#define CP_COMMIT() asm volatile("cp.async.commit_group;" ::: "memory")

__device__ __forceinline__ void ldsm_x4(uint32_t* r, uint32_t a) {
    asm volatile("ldmatrix.sync.aligned.m8n8.x4.shared.b16 {%0,%1,%2,%3}, [%4];"
                 : "=r"(r[0]), "=r"(r[1]), "=r"(r[2]), "=r"(r[3]) : "r"(a));
}
// fp16-accumulating MMA: d = {c0c1, c2c3} packed half2 regs
__device__ __forceinline__ void mma16816h(uint32_t* d, const uint32_t* a,
                                          uint32_t b0, uint32_t b1) {
    asm volatile(
        "mma.sync.aligned.m16n8k16.row.col.f16.f16.f16.f16 "
        "{%0,%1}, {%2,%3,%4,%5}, {%6,%7}, {%0,%1};"
        : "+r"(d[0]), "+r"(d[1])
        : "r"(a[0]), "r"(a[1]), "r"(a[2]), "r"(a[3]), "r"(b0), "r"(b1));
}

// ---------------------------------------------------------------------------
// Merged: layer0 jets (blocks 0..NSAMP-1) + weight transpose/convert + acc
// zero (blocks NSAMP..NSAMP+767).
__global__ void k_prep0(const float* __restrict__ W0, const float* __restrict__ b0,
                        const float* __restrict__ x,  const float* __restrict__ t,
                        const float* __restrict__ W1, const float* __restrict__ W2,
                        const float* __restrict__ W3) {
    int blk = blockIdx.x;
    int j = threadIdx.x;
    if (blk >= NSAMP) {
        int wb = blk - NSAMP;          // 0..767
        int w = wb >> 8;               // weight matrix id
        int n = wb & 255;
        const float* W = (w == 0) ? W1 : ((w == 1) ? W2 : W3);
        g_Wt[w][n * HIDN + j] = __float2half(W[j * HIDN + n]);
        if (wb == 0 && j < 5) g_acc[j] = 0.0;
        return;
    }
    int n = blk;
    float x0 = x[2 * n], x1 = x[2 * n + 1], tv = t[n];
    float w0 = W0[j], w1 = W0[HIDN + j], w2 = W0[2 * HIDN + j];
    float zv = fmaf(x0, w0, fmaf(x1, w1, fmaf(tv, w2, b0[j])));
    float y = tanh_hw(zv);
    float yp = 1.0f - y * y;
    float ypp = -2.0f * y * yp;
    size_t base = ((size_t)n * 7) * HIDN + j;
    g_A0[base]            = __float2half(y);
    g_A0[base + HIDN]     = __float2half(yp * w0);
    g_A0[base + 2 * HIDN] = __float2half(yp * w1);
    g_A0[base + 3 * HIDN] = __float2half(yp * w2);
    g_A0[base + 4 * HIDN] = __float2half(ypp * w0 * w0);
    g_A0[base + 5 * HIDN] = __float2half(ypp * w0 * w1);
    g_A0[base + 6 * HIDN] = __float2half(ypp * w1 * w1);
}

// ---------------------------------------------------------------------------
// Fused fp16 GEMM + jet-tanh activation layer (ping-pong A buffers).
// CTA: 256 threads / 8 warps; tile 112 x 256 (full N); warp tile 7mt x 4nt.
// fp16 accumulators. K in 4 chunks of 64, 2-stage cp.async double buffer.
// last=1: instead of storing activations, run the physics epilogue inline.
#define ACH   14336                 // A chunk: 112 rows x 128B
#define BCH   32768                 // B chunk: 256 rows x 128B
#define BUF   (ACH + BCH)           // 47104
#define SMEMT (2 * BUF)             // 94208
#define ZS    264                   // z staging stride in halfs (528B = 33*16)

__global__ void __launch_bounds__(256, 2) k_gemm(const __half* __restrict__ Asrc,
                                                 __half* __restrict__ Adst,
                                                 const __half* __restrict__ Bw,
                                                 const float* __restrict__ bias,
                                                 const float* __restrict__ W4,
                                                 const float* __restrict__ b4,
                                                 const float* __restrict__ x,
                                                 const float* __restrict__ t,
                                                 float* __restrict__ out,
                                                 int last) {
    extern __shared__ char smem[];
    uint32_t sb = smem_u32(smem);
    int tid = threadIdx.x;
    int warp = tid >> 5, lane = tid & 31;
    int row0 = blockIdx.x * MT;

    uint32_t acc[7][4][2];   // fp16x2 accumulators
#pragma unroll
    for (int mt = 0; mt < 7; mt++)
#pragma unroll
        for (int nt = 0; nt < 4; nt++) { acc[mt][nt][0] = 0u; acc[mt][nt][1] = 0u; }

    auto load_chunk = [&](int c) {
        uint32_t base = sb + (c & 1) * BUF;
        int k0 = c * 64;
#pragma unroll
        for (int idx = tid; idx < 896; idx += 256) {
            int r = idx >> 3, u = idx & 7;
            cpasync16(base + sw128(r * 128 + u * 16),
                      Asrc + (size_t)(row0 + r) * HIDN + k0 + u * 8);
        }
#pragma unroll
        for (int idx = tid; idx < 2048; idx += 256) {
            int r = idx >> 3, u = idx & 7;
            cpasync16(base + ACH + sw128(r * 128 + u * 16),
                      Bw + (size_t)r * HIDN + k0 + u * 8);
        }
        CP_COMMIT();
    };

    load_chunk(0);
    load_chunk(1);

    int l8 = lane & 7;
    int qm8  = ((lane >> 3) & 1) * 8;   // +8 row for mats 1,3
    uint32_t qk16 = (lane >> 4) * 16;   // +16B (k+8) for mats 2,3

    uint32_t aoff0 = sw128((qm8 + l8) * 128) ^ qk16;
    uint32_t boff0 = ACH + (sw128((warp * 32 + qm8 + l8) * 128) ^ qk16);
    uint32_t boff1 = ACH + (sw128((warp * 32 + 16 + qm8 + l8) * 128) ^ qk16);

    uint32_t af[2][4];       // rolling A fragments
    uint32_t bf[2][8];       // double-buffered B fragments (per ks)

#pragma unroll
    for (int c = 0; c < 4; c++) {
        if (c < 3) asm volatile("cp.async.wait_group 1;" ::: "memory");
        else       asm volatile("cp.async.wait_group 0;" ::: "memory");
        __syncthreads();

        uint32_t bufb = sb + (c & 1) * BUF;

        ldsm_x4(&bf[0][0], bufb + boff0);
        ldsm_x4(&bf[0][4], bufb + boff1);
        ldsm_x4(af[0], bufb + aoff0);

        int p = 0;
#pragma unroll
        for (int ks = 0; ks < 4; ks++) {
            uint32_t kxn = ((ks + 1) & 3) * 32;
            const uint32_t* bcur = bf[ks & 1];
#pragma unroll
            for (int mt = 0; mt < 7; mt++) {
                if (mt < 6) {
                    uint32_t kx = ks * 32;
                    ldsm_x4(af[p ^ 1], bufb + ((aoff0 + (mt + 1) * 2048) ^ kx));
                } else if (ks < 3) {
                    ldsm_x4(af[p ^ 1], bufb + (aoff0 ^ kxn));
                }
                if (mt == 1 && ks < 3) {
                    ldsm_x4(&bf[(ks + 1) & 1][0], bufb + (boff0 ^ kxn));
                    ldsm_x4(&bf[(ks + 1) & 1][4], bufb + (boff1 ^ kxn));
                }
                const uint32_t* a = af[p];
                mma16816h(acc[mt][0], a, bcur[0], bcur[2]);
                mma16816h(acc[mt][1], a, bcur[1], bcur[3]);
                mma16816h(acc[mt][2], a, bcur[4], bcur[6]);
                mma16816h(acc[mt][3], a, bcur[5], bcur[7]);
                p ^= 1;
            }
        }
        if (c + 2 < 4) { __syncthreads(); load_chunk(c + 2); }
    }
    __syncthreads();

    // ---- stage z (pre-activation, fp16) into smem ----
    __half* zb = (__half*)smem;
#pragma unroll
    for (int mt = 0; mt < 7; mt++)
#pragma unroll
        for (int nt = 0; nt < 4; nt++)
#pragma unroll
            for (int e = 0; e < 2; e++) {
                int r = mt * 16 + (lane >> 2) + e * 8;
                int col = warp * 32 + nt * 8 + ((lane & 3) << 1);
                *(uint32_t*)(zb + r * ZS + col) = acc[mt][nt][e];
            }
    __syncthreads();

    if (!last) {
        // half2-vectorized activation -> global fp16
        for (int i = tid; i < SPC * (HIDN / 2); i += 256) {
            int nl = i >> 7, jp = (i & 127) * 2;
            const __half* zrow = zb + (nl * 7) * ZS + jp;
            float2 zv2  = __half22float2(*(const __half2*)(zrow));
            float2 zg1  = __half22float2(*(const __half2*)(zrow + ZS));
            float2 zg2  = __half22float2(*(const __half2*)(zrow + 2 * ZS));
            float2 zg3  = __half22float2(*(const __half2*)(zrow + 3 * ZS));
            float2 zs11 = __half22float2(*(const __half2*)(zrow + 4 * ZS));
            float2 zs12 = __half22float2(*(const __half2*)(zrow + 5 * ZS));
            float2 zs22 = __half22float2(*(const __half2*)(zrow + 6 * ZS));
            float b0v = bias[jp], b1v = bias[jp + 1];

            float ya = tanh_hw(zv2.x + b0v), yb = tanh_hw(zv2.y + b1v);
            float ypa = 1.0f - ya * ya,      ypb = 1.0f - yb * yb;
            float yppa = -2.0f * ya * ypa,   yppb = -2.0f * yb * ypb;

            __half2* dst = (__half2*)(Adst + ((size_t)(row0 + nl * 7)) * HIDN + jp);
            dst[0]              = __floats2half2_rn(ya, yb);
            dst[HIDN / 2]       = __floats2half2_rn(ypa * zg1.x, ypb * zg1.y);
            dst[2 * (HIDN / 2)] = __floats2half2_rn(ypa * zg2.x, ypb * zg2.y);
            dst[3 * (HIDN / 2)] = __floats2half2_rn(ypa * zg3.x, ypb * zg3.y);
            dst[4 * (HIDN / 2)] = __floats2half2_rn(
                fmaf(yppa * zg1.x, zg1.x, ypa * zs11.x),
                fmaf(yppb * zg1.y, zg1.y, ypb * zs11.y));
            dst[5 * (HIDN / 2)] = __floats2half2_rn(
                fmaf(yppa * zg1.x, zg2.x, ypa * zs12.x),
                fmaf(yppb * zg1.y, zg2.y, ypb * zs12.y));
            dst[6 * (HIDN / 2)] = __floats2half2_rn(
                fmaf(yppa * zg2.x, zg2.x, ypa * zs22.x),
                fmaf(yppb * zg2.y, zg2.y, ypb * zs22.y));
        }
        return;
    }

    // ==== last layer: physics epilogue directly from z-staging ====
    double* sacc = (double*)(smem + 60000);   // past zb (112*528=59136)
    if (tid < 5) sacc[tid] = 0.0;
    __syncthreads();

    // per-lane W4 slice (k = lane*8..lane*8+7) and layer-3 bias slice
    float wreg[8][3];
    float breg[8];
#pragma unroll
    for (int i = 0; i < 8; i++) {
        int k = lane * 8 + i;
        wreg[i][0] = W4[k * 3 + 0];
        wreg[i][1] = W4[k * 3 + 1];
        wreg[i][2] = W4[k * 3 + 2];
        breg[i] = bias[k];
    }

    for (int s = 0; s < 2; s++) {
        int nl = warp * 2 + s;
        int n = blockIdx.x * SPC + nl;

        float o[7][3];
#pragma unroll
        for (int c = 0; c < 7; c++)
#pragma unroll
            for (int a = 0; a < 3; a++) o[c][a] = 0.0f;

        const __half* zbase = zb + (nl * 7) * ZS + lane * 8;
#pragma unroll
        for (int g = 0; g < 4; g++) {
            float2 z[7];
#pragma unroll
            for (int c = 0; c < 7; c++)
                z[c] = __half22float2(*(const __half2*)(zbase + c * ZS + g * 2));
#pragma unroll
            for (int e = 0; e < 2; e++) {
                int i = g * 2 + e;
                float zv  = (e ? z[0].y : z[0].x) + breg[i];
                float zg1 = e ? z[1].y : z[1].x;
                float zg2 = e ? z[2].y : z[2].x;
                float zg3 = e ? z[3].y : z[3].x;
                float zs11 = e ? z[4].y : z[4].x;
                float zs12 = e ? z[5].y : z[5].x;
                float zs22 = e ? z[6].y : z[6].x;
                float y = tanh_hw(zv);
                float yp = 1.0f - y * y;
                float ypp = -2.0f * y * yp;
                float H0 = y;
                float H1 = yp * zg1;
                float H2 = yp * zg2;
                float H3 = yp * zg3;
                float H4 = fmaf(ypp * zg1, zg1, yp * zs11);
                float H5 = fmaf(ypp * zg1, zg2, yp * zs12);
                float H6 = fmaf(ypp * zg2, zg2, yp * zs22);
#pragma unroll
                for (int a = 0; a < 3; a++) {
                    o[0][a] = fmaf(H0, wreg[i][a], o[0][a]);
                    o[1][a] = fmaf(H1, wreg[i][a], o[1][a]);
                    o[2][a] = fmaf(H2, wreg[i][a], o[2][a]);
                    o[3][a] = fmaf(H3, wreg[i][a], o[3][a]);
                    o[4][a] = fmaf(H4, wreg[i][a], o[4][a]);
                    o[5][a] = fmaf(H5, wreg[i][a], o[5][a]);
                    o[6][a] = fmaf(H6, wreg[i][a], o[6][a]);
                }
            }
        }
#pragma unroll
        for (int c = 0; c < 7; c++)
#pragma unroll
            for (int a = 0; a < 3; a++)
#pragma unroll
                for (int off = 16; off > 0; off >>= 1)
                    o[c][a] += __shfl_xor_sync(0xFFFFFFFFu, o[c][a], off);

        if (lane == 0) {
            float s0  = o[0][0] + b4[0];
            float s1v = o[0][1] + b4[1];
            float s2v = o[0][2] + b4[2];
            float D00 = o[1][0], D01 = o[2][0], D0t = o[3][0];
            float S000 = o[4][0], S011 = o[6][0];
            float D10 = o[1][1], D11 = o[2][1];
            float S100 = o[4][1], S101 = o[5][1], S111 = o[6][1];
            float D20 = o[1][2], D21 = o[2][2];
            float S200 = o[4][2], S201 = o[5][2], S211 = o[6][2];

            float x1 = x[2 * n + 1];
            float tt = t[n];
            float q  = x1 * (x1 - 1.0f);
            float qp = 2.0f * x1 - 1.0f;
            float t3 = tt / 3.0f;

            float ux0 = t3 * q * D10;
            float ux1 = t3 * (qp * s1v + q * D11);
            float uy0 = tt * q * D20;
            float uy1 = tt * (qp * s2v + q * D21) + tt;

            float e00 = ux0, e11 = uy1, e01 = 0.5f * (ux1 + uy0);

            float ux00 = t3 * q * S100;
            float ux01 = t3 * (qp * D10 + q * S101);
            float ux11 = t3 * (2.0f * s1v + 2.0f * qp * D11 + q * S111);
            float uy00 = tt * q * S200;
            float uy01 = tt * (qp * D20 + q * S201);
            float uy11 = tt * (2.0f * s2v + 2.0f * qp * D21 + q * S211);

            float e00_0 = ux00, e00_1 = ux01;
            float e11_0 = uy01, e11_1 = uy11;
            float e01_0 = 0.5f * (ux01 + uy00);
            float e01_1 = 0.5f * (ux11 + uy01);

            float trc  = e00 + e11;
            float tr_0 = e00_0 + e11_0;
            float tr_1 = e00_1 + e11_1;

            float phi = 1.0f / (1.0f + expf(-s0));
            float sp  = phi * (1.0f - phi);
            float spp = sp * (1.0f - 2.0f * phi);
            float p0 = sp * D00, p1 = sp * D01, pt = sp * D0t;
            float p00 = spp * D00 * D00 + sp * S000;
            float p11 = spp * D01 * D01 + sp * S011;
            float lap = p00 + p11;

            float A  = fmaxf(trc, 0.0f);
            float Bn = fmaxf(-trc, 0.0f);
            float ppos = (trc > 0.0f) ? 1.0f : 0.0f;
            float pneg = (trc < 0.0f) ? 1.0f : 0.0f;
            float dd = e00 - e11;

            float omp = 1.0f - phi;
            float h   = omp * omp;
            float g   = h + 1e-6f;
            float hp0 = -2.0f * omp * p0;
            float hp1 = -2.0f * omp * p1;

            float P00 = 2.0f * A + dd;
            float P11 = 2.0f * A - dd;
            float P01 = 2.0f * e01;
            float s00 = g * P00 - 2.0f * Bn;
            float s11c = g * P11 - 2.0f * Bn;
            float s01 = g * P01;

            float P00_0 = 2.0f * ppos * tr_0 + (e00_0 - e11_0);
            float P11_1 = 2.0f * ppos * tr_1 - (e00_1 - e11_1);
            float P01_0 = 2.0f * e01_0;
            float P01_1 = 2.0f * e01_1;

            float s00_0 = hp0 * P00 + g * P00_0 + 2.0f * pneg * tr_0;
            float s11_1 = hp1 * P11 + g * P11_1 + 2.0f * pneg * tr_1;
            float s01_0 = hp0 * P01 + g * P01_0;
            float s01_1 = hp1 * P01 + g * P01_1;

            float res0 = hp0 * s00 + h * s00_0 + hp1 * s01 + h * s01_1;
            float res1 = hp0 * s01 + h * s01_0 + hp1 * s11c + h * s11_1;

            float psip = A * A + 0.5f * dd * dd + 2.0f * e01 * e01;
            float psin = Bn * Bn;

            const float GCc = 0.0027f, Lc = 0.02f;
            float pf = GCc * (phi / Lc - Lc * lap) - 2.0f * omp * psip;
            float dphidt = pt;
            bool mask_pos = (fabsf(dphidt) <= 1e-3f) && (fabsf(phi - 1.0f) > 1e-3f);
            bool mask_neg = (fabsf(phi - 1.0f) <= 1e-3f);
            float respf = mask_pos ? fmaxf(-pf, 0.0f) : (mask_neg ? fmaxf(pf, 0.0f) : pf);

            float rese = omp * 2.0f * psip + psin
                       + GCc * (phi * phi / (2.0f * Lc) + 0.5f * Lc * (p0 * p0 + p1 * p1));
            float rirr = fmaxf(-dphidt, 0.0f);

            atomicAdd(&sacc[0], (double)(res0 * res0));
            atomicAdd(&sacc[1], (double)(res1 * res1));
            atomicAdd(&sacc[2], (double)(respf * respf));
            atomicAdd(&sacc[3], (double)rese);
            atomicAdd(&sacc[4], (double)rirr);
        }
    }
    __syncthreads();
    if (tid < 5) atomicAdd(&g_acc[tid], sacc[tid]);

    // merged finalize: last CTA computes the outputs
    if (tid == 0) {
        __threadfence();
        unsigned v = atomicAdd(&g_done, 1u);
        if (v == gridDim.x - 1) {
            g_done = 0;   // reset for graph replay
            double S0 = g_acc[0], S1 = g_acc[1], Spf = g_acc[2];
            double Se = g_acc[3], Si = g_acc[4];
            double Nn = (double)NSAMP;
            double mse0 = S0 / Nn, mse1 = S1 / Nn;
            double m  = 0.5 * (mse0 + mse1);
            double w0 = m / (mse0 + 1e-6);
            double w1 = m / (mse1 + 1e-6);
            out[0] = (float)(w0 * mse0 + w1 * mse1);
            out[1] = (float)(Spf / Nn);
            out[2] = (float)log(Se);
            out[3] = (float)(Si / Nn);
        }
    }
}

// ---------------------------------------------------------------------------
extern "C" void kernel_launch(void* const* d_in, const int* in_sizes, int n_in,
                              void* d_out, int out_size) {
    const float *W[5], *b[5];
    if (n_in >= 2 && in_sizes[1] == HIDN) {
        for (int i = 0; i < 5; i++) {
            W[i] = (const float*)d_in[2 * i];
            b[i] = (const float*)d_in[2 * i + 1];
        }
    } else {
        for (int i = 0; i < 5; i++) {
            W[i] = (const float*)d_in[i];
            b[i] = (const float*)d_in[5 + i];
        }
    }
    const float* x = (const float*)d_in[10];
    const float* t = (const float*)d_in[11];

    __half *pA0, *pA1, *pW;
    cudaGetSymbolAddress((void**)&pA0, g_A0);
    cudaGetSymbolAddress((void**)&pA1, g_A1);
    cudaGetSymbolAddress((void**)&pW,  g_Wt);

    static bool attr_done = false;
    if (!attr_done) {
        cudaFuncSetAttribute(k_gemm, cudaFuncAttributeMaxDynamicSharedMemorySize, SMEMT);
        attr_done = true;
    }

    k_prep0<<<NSAMP + 768, 256>>>(W[0], b[0], x, t, W[1], W[2], W[3]);

    const int GRID = MTOT / MT;      // 512
    k_gemm<<<GRID, 256, SMEMT>>>(pA0, pA1, pW,                   b[1],
                                 W[4], b[4], x, t, (float*)d_out, 0);
    k_gemm<<<GRID, 256, SMEMT>>>(pA1, pA0, pW + HIDN * HIDN,     b[2],
                                 W[4], b[4], x, t, (float*)d_out, 0);
    k_gemm<<<GRID, 256, SMEMT>>>(pA0, pA1, pW + 2 * HIDN * HIDN, b[3],
                                 W[4], b[4], x, t, (float*)d_out, 1);
}